// round 15
// baseline (speedup 1.0000x reference)
#include <cuda_runtime.h>
#include <cuda_bf16.h>
#include <math.h>
#include <stdint.h>

#define BB 8
#define CC 256
#define DD 128
#define KK 1024
#define NNN 4096
#define GAMMA 0.99f
#define OMG 0.01f

#define OUT_NUM (BB*DD*NNN)          /* 4194304 */
#define OUT_DEN (OUT_NUM + KK*DD)    /* 4325376 */

typedef unsigned long long u64t;

// ---------------- device globals (no runtime alloc allowed) ----------------
__device__ __align__(128) float g_ze[BB*DD*NNN];                 // 16 MB fp32 ze
__device__ float g_qsq[KK], g_qs[KK];
__device__ float g_zesq[BB*NNN], g_za[BB*NNN];
__device__ __align__(128) __nv_bfloat16 g_emb3[8*3*128*128];     // emb split images
__device__ __align__(128) __nv_bfloat16 g_zt3[BB*32*3*128*128];  // ze^T split images

// packed fp32x2 FMA (ze kernel)
#define FMA2(acc, a, b) \
    asm("fma.rn.f32x2 %0, %1, %2, %0;" : "+l"(acc) : "l"(a), "l"(b))
__device__ __forceinline__ float fold2(u64t v) {
    float lo, hi;
    asm("mov.b64 {%0, %1}, %2;" : "=f"(lo), "=f"(hi) : "l"(v));
    return lo + hi;
}

__device__ __forceinline__ uint32_t smem_u32(const void* p) {
    uint32_t a;
    asm("{ .reg .u64 t; cvta.to.shared.u64 t, %1; cvt.u32.u64 %0, t; }" : "=r"(a) : "l"(p));
    return a;
}

// ---------------- mma.sync / ldmatrix (arch-generic, sm_80+) ----------------
#define LDSM4(r, addr) \
    asm volatile("ldmatrix.sync.aligned.m8n8.x4.shared.b16 {%0,%1,%2,%3}, [%4];" \
        : "=r"((r)[0]), "=r"((r)[1]), "=r"((r)[2]), "=r"((r)[3]) : "r"(addr))

#define MMA16816(c, a, b0, b1) \
    asm volatile("mma.sync.aligned.m16n8k16.row.col.f32.bf16.bf16.f32 " \
        "{%0,%1,%2,%3}, {%4,%5,%6,%7}, {%8,%9}, {%0,%1,%2,%3};" \
        : "+f"((c)[0]), "+f"((c)[1]), "+f"((c)[2]), "+f"((c)[3]) \
        : "r"((a)[0]), "r"((a)[1]), "r"((a)[2]), "r"((a)[3]), "r"(b0), "r"(b1))

// byte offset inside a 128x128-bf16 image: [r][d], 256B rows,
// 16B chunks XOR-swizzled by (r&7) -> conflict-free ldmatrix
__device__ __forceinline__ int img_off(int r, int c) {
    return r * 256 + ((((c >> 3) ^ (r & 7))) << 4) + ((c & 7) << 1);
}

__device__ __forceinline__ void split3(float x, __nv_bfloat16& e0,
                                       __nv_bfloat16& e1, __nv_bfloat16& e2) {
    e0 = __float2bfloat16(x);
    float r1 = x - __bfloat162float(e0);
    e1 = __float2bfloat16(r1);
    float r2 = r1 - __bfloat162float(e1);
    e2 = __float2bfloat16(r2);
}

__device__ __forceinline__ float2 bf2f(uint32_t u) {
    __nv_bfloat162 h = *reinterpret_cast<__nv_bfloat162*>(&u);
    return make_float2(__bfloat162float(h.x), __bfloat162float(h.y));
}

// ============================================================================
// prep: EMA init + codebook norms + emb bf16x3 split images
// ============================================================================
__global__ void prep_kernel(const float* __restrict__ emb,
                            const float* __restrict__ ema_numer,
                            const float* __restrict__ ema_denom,
                            float* __restrict__ out) {
    int bid = blockIdx.x, tid = threadIdx.x;
    if (bid < 128) {
        int idx = bid * 256 + tid;
        float4 v = reinterpret_cast<const float4*>(ema_numer)[idx];
        reinterpret_cast<float4*>(out + OUT_NUM)[idx] =
            make_float4(GAMMA * v.x, GAMMA * v.y, GAMMA * v.z, GAMMA * v.w);
    } else if (bid < 256) {
        int q = (bid - 128) * 8 + (tid >> 5);
        int lane = tid & 31;
        float4 v = reinterpret_cast<const float4*>(emb)[q * 32 + lane];
        float s = v.x * v.x + v.y * v.y + v.z * v.z + v.w * v.w;
#pragma unroll
        for (int o = 16; o; o >>= 1) s += __shfl_xor_sync(~0u, s, o);
        if (lane == 0) {
            g_qsq[q] = s;
            g_qs[q]  = sqrtf(s);
            out[OUT_DEN + q] = GAMMA * ema_denom[q];
        }
    } else {
        int kt = bid - 256;                       // code tile 0..7
        char* base = (char*)(g_emb3 + (size_t)kt * 3 * 16384);
        for (int t = tid; t < 128 * 128; t += 256) {
            int r = t >> 7, c = t & 127;
            float x = emb[(kt * 128 + r) * DD + c];
            __nv_bfloat16 e0, e1, e2;
            split3(x, e0, e1, e2);
            int o = img_off(r, c);
            *(__nv_bfloat16*)(base + o)         = e0;
            *(__nv_bfloat16*)(base + 32768 + o) = e1;
            *(__nv_bfloat16*)(base + 65536 + o) = e2;
        }
    }
}

// ============================================================================
// ze = W_lin @ z per batch (fp32 SIMT)
// ============================================================================
__global__ void __launch_bounds__(512)
ze_kernel(const float* __restrict__ z, const float* __restrict__ W) {
    extern __shared__ float sm[];
    float* sW = sm;
    float* sZ = sm + 128 * 256;
    int tid = threadIdx.x;
    int tx = tid & 31, ty = tid >> 5;
    int n0 = blockIdx.x * 128, b = blockIdx.y;
    int t7 = tx & 7;

#pragma unroll
    for (int t = 0; t < 16; ++t) {
        int v = tid + t * 512;
        reinterpret_cast<float4*>(sW)[v] = reinterpret_cast<const float4*>(W)[v];
    }

    u64t acc[8][4];
#pragma unroll
    for (int i = 0; i < 8; ++i)
#pragma unroll
        for (int j = 0; j < 4; ++j) acc[i][j] = 0ull;

    const float* zb = z + (size_t)b * CC * NNN + n0;
    for (int cc0 = 0; cc0 < CC; cc0 += 32) {
        __syncthreads();
#pragma unroll
        for (int t = 0; t < 2; ++t) {
            int v = tid + t * 512;
            int r = v >> 5, nn = (v & 31) << 2;
            float4 val = *reinterpret_cast<const float4*>(zb + (size_t)(cc0 + r) * NNN + nn);
            int c4 = r >> 2, cm = r & 3;
            sZ[(nn + 0) * 32 + ((c4 ^ ((nn + 0) & 7)) << 2) + cm] = val.x;
            sZ[(nn + 1) * 32 + ((c4 ^ ((nn + 1) & 7)) << 2) + cm] = val.y;
            sZ[(nn + 2) * 32 + ((c4 ^ ((nn + 2) & 7)) << 2) + cm] = val.z;
            sZ[(nn + 3) * 32 + ((c4 ^ ((nn + 3) & 7)) << 2) + cm] = val.w;
        }
        __syncthreads();
#pragma unroll
        for (int c4 = 0; c4 < 8; ++c4) {
            ulonglong2 zv[4];
#pragma unroll
            for (int j = 0; j < 4; ++j)
                zv[j] = *reinterpret_cast<const ulonglong2*>(
                    sZ + (32 * j + tx) * 32 + ((c4 ^ t7) << 2));
#pragma unroll
            for (int i = 0; i < 8; ++i) {
                ulonglong2 wv = *reinterpret_cast<const ulonglong2*>(
                    sW + (16 * i + ty) * 256 + cc0 + (c4 << 2));
#pragma unroll
                for (int j = 0; j < 4; ++j) {
                    FMA2(acc[i][j], wv.x, zv[j].x);
                    FMA2(acc[i][j], wv.y, zv[j].y);
                }
            }
        }
    }
    float* zo = g_ze + (size_t)b * DD * NNN + n0;
#pragma unroll
    for (int i = 0; i < 8; ++i)
#pragma unroll
        for (int j = 0; j < 4; ++j)
            zo[(size_t)(16 * i + ty) * NNN + 32 * j + tx] = fold2(acc[i][j]);
}

// ============================================================================
// zesplit: g_ze tile -> ze^T bf16x3 swizzled images + zesq/za
// ============================================================================
__global__ void __launch_bounds__(256)
zesplit_kernel() {
    extern __shared__ char smc[];
    float* s_f = (float*)smc;                 // [128][129] fp32
    char*  s_img = smc + 66048;               // 3 x 32768 images
    int tid = threadIdx.x;
    int b = blockIdx.y, nt = blockIdx.x, n0 = nt * 128;
    const float* zeg = g_ze + (size_t)b * DD * NNN + n0;

    for (int t = tid; t < 4096; t += 256) {
        int d = t >> 5, n4 = (t & 31) << 2;
        float4 v = *(const float4*)(zeg + (size_t)d * NNN + n4);
        float* row = s_f + d * 129;
        row[n4] = v.x; row[n4 + 1] = v.y; row[n4 + 2] = v.z; row[n4 + 3] = v.w;
    }
    __syncthreads();

    int n = tid & 127, dh = (tid >> 7) << 6;
    float ssum = 0.f;
#pragma unroll 4
    for (int dd = 0; dd < 64; ++dd) {
        int d = dh + dd;
        float x = s_f[d * 129 + n];
        ssum += x * x;
        __nv_bfloat16 e0, e1, e2;
        split3(x, e0, e1, e2);
        int o = img_off(n, d);
        *(__nv_bfloat16*)(s_img + o)         = e0;
        *(__nv_bfloat16*)(s_img + 32768 + o) = e1;
        *(__nv_bfloat16*)(s_img + 65536 + o) = e2;
    }
    __syncthreads();
    ((float*)smc)[tid] = ssum;
    __syncthreads();
    uint4* dst = (uint4*)(g_zt3 + (size_t)(b * 32 + nt) * 3 * 16384);
    const uint4* src = (const uint4*)s_img;
    for (int t = tid; t < 6144; t += 256) dst[t] = src[t];
    if (tid < 128) {
        float s = ((float*)smc)[tid] + ((float*)smc)[tid + 128];
        g_zesq[b * NNN + n0 + tid] = s;
        g_za[b * NNN + n0 + tid]   = sqrtf(s);
    }
}

// ============================================================================
// vq: HMMA bf16x3 error-free GEMM + argmin + gather + EMA scatter
// grid (32, 8), 512 threads (16 warps = 4m x 4k), ~196 KB smem
// ============================================================================
#define SM_QSQ  0
#define SM_QS   512
#define SM_ZESQ 1024
#define SM_ZA   1536
#define SM_IDX  2048
#define SM_A    4096
#define SM_B    102400
#define VQ_SMEM 200704

__global__ void __launch_bounds__(512)
vq_kernel(const float* __restrict__ emb, float* __restrict__ out) {
    extern __shared__ char smc[];
    uint32_t sb = smem_u32(smc);
    int tid = threadIdx.x, l = tid & 31, wid = tid >> 5;
    int b = blockIdx.y, nt = blockIdx.x, n0 = nt * 128;

    // prologue: A (ze^T) images + zesq/za
    {
        const uint4* asrc = (const uint4*)(g_zt3 + (size_t)(b * 32 + nt) * 3 * 16384);
        uint4* adst = (uint4*)(smc + SM_A);
        for (int t = tid; t < 6144; t += 512) adst[t] = asrc[t];
        if (tid < 128) {
            ((float*)(smc + SM_ZESQ))[tid] = g_zesq[b * NNN + n0 + tid];
            ((float*)(smc + SM_ZA))[tid]   = g_za[b * NNN + n0 + tid];
        }
    }
    __syncthreads();

    int warp_m = wid & 3, warp_k = wid >> 2;
    int sub = l >> 3, l7 = l & 7, lq = l & 3, gr = l >> 2;
    uint32_t xA = (uint32_t)(sub >> 1), xB = (uint32_t)(sub & 1);
    uint32_t abase0 = sb + SM_A + (uint32_t)(warp_m * 32 + (sub & 1) * 8 + l7) * 256;
    uint32_t abase1 = abase0 + 16 * 256;
    uint32_t bbase0 = sb + SM_B + (uint32_t)(warp_k * 32 + (sub >> 1) * 8 + l7) * 256;
    uint32_t bbase1 = bbase0 + 16 * 256;

    float zesq_r[4], za_r[4];
#pragma unroll
    for (int s = 0; s < 4; ++s) {
        int row = warp_m * 32 + (s >> 1) * 16 + gr + (s & 1) * 8;
        zesq_r[s] = ((float*)(smc + SM_ZESQ))[row];
        za_r[s]   = ((float*)(smc + SM_ZA))[row];
    }

    float bn[4], bd[4];
    int bi[4];
#pragma unroll
    for (int s = 0; s < 4; ++s) { bn[s] = 1e30f; bd[s] = 1.f; bi[s] = 0; }

    int jb = warp_k * 32 + 2 * lq;

    for (int kt = 0; kt < 8; ++kt) {
        __syncthreads();
        {
            const uint4* bsrc = (const uint4*)(g_emb3 + (size_t)kt * 3 * 16384);
            uint4* bdst = (uint4*)(smc + SM_B);
            for (int t = tid; t < 6144; t += 512) bdst[t] = bsrc[t];
            if (tid < 128) {
                ((float*)(smc + SM_QSQ))[tid] = g_qsq[kt * 128 + tid];
                ((float*)(smc + SM_QS))[tid]  = g_qs[kt * 128 + tid];
            }
        }
        __syncthreads();

        float acc[2][4][4];
#pragma unroll
        for (int mi = 0; mi < 2; ++mi)
#pragma unroll
            for (int ni = 0; ni < 4; ++ni)
#pragma unroll
                for (int c = 0; c < 4; ++c) acc[mi][ni][c] = 0.f;

#define MMA_ALL(B0, B1) do { \
        MMA16816(acc[0][0], A0, B0[0], B0[1]); \
        MMA16816(acc[0][1], A0, B0[2], B0[3]); \
        MMA16816(acc[0][2], A0, B1[0], B1[1]); \
        MMA16816(acc[0][3], A0, B1[2], B1[3]); \
        MMA16816(acc[1][0], A1, B0[0], B0[1]); \
        MMA16816(acc[1][1], A1, B0[2], B0[3]); \
        MMA16816(acc[1][2], A1, B1[0], B1[1]); \
        MMA16816(acc[1][3], A1, B1[2], B1[3]); } while (0)

#pragma unroll
        for (int ks = 0; ks < 8; ++ks) {
            uint32_t ca = (uint32_t)(((2 * ks + xA) ^ (uint32_t)l7) << 4);
            uint32_t cb = (uint32_t)(((2 * ks + xB) ^ (uint32_t)l7) << 4);
            uint32_t A0[4], A1[4], B0[4], B1[4];
            // p = 0 : q = 0,1,2
            LDSM4(A0, abase0 + ca); LDSM4(A1, abase1 + ca);
            LDSM4(B0, bbase0 + cb);           LDSM4(B1, bbase1 + cb);           MMA_ALL(B0, B1);
            LDSM4(B0, bbase0 + 32768 + cb);   LDSM4(B1, bbase1 + 32768 + cb);   MMA_ALL(B0, B1);
            LDSM4(B0, bbase0 + 65536 + cb);   LDSM4(B1, bbase1 + 65536 + cb);   MMA_ALL(B0, B1);
            // p = 1 : q = 0,1
            LDSM4(A0, abase0 + 32768 + ca); LDSM4(A1, abase1 + 32768 + ca);
            LDSM4(B0, bbase0 + cb);           LDSM4(B1, bbase1 + cb);           MMA_ALL(B0, B1);
            LDSM4(B0, bbase0 + 32768 + cb);   LDSM4(B1, bbase1 + 32768 + cb);   MMA_ALL(B0, B1);
            // p = 2 : q = 0
            LDSM4(A0, abase0 + 65536 + ca); LDSM4(A1, abase1 + 65536 + ca);
            LDSM4(B0, bbase0 + cb);           LDSM4(B1, bbase1 + cb);           MMA_ALL(B0, B1);
        }

        // argmin update from c-fragments
        float qq[4][2], qn[4][2];
#pragma unroll
        for (int ni = 0; ni < 4; ++ni)
#pragma unroll
            for (int c = 0; c < 2; ++c) {
                int j = jb + ni * 8 + c;
                qq[ni][c] = ((float*)(smc + SM_QSQ))[j];
                qn[ni][c] = ((float*)(smc + SM_QS))[j];
            }
#pragma unroll
        for (int mi = 0; mi < 2; ++mi)
#pragma unroll
            for (int h = 0; h < 2; ++h) {
                int s = mi * 2 + h;
#pragma unroll
                for (int ni = 0; ni < 4; ++ni)
#pragma unroll
                    for (int c = 0; c < 2; ++c) {
                        float dot = acc[mi][ni][2 * h + c];
                        float num = fmaxf(zesq_r[s] + qq[ni][c] - 2.f * dot, 0.f);
                        float den = za_r[s] + qn[ni][c];
                        float d2 = den * den;
                        if (num * bd[s] < bn[s] * d2) {
                            bn[s] = num; bd[s] = d2;
                            bi[s] = kt * 128 + jb + ni * 8 + c;
                        }
                    }
            }
    }
    __syncthreads();

    // ---- cross-thread argmin reduction (overlay on s_B) ----
    float* rn = (float*)(smc + SM_B);
    float* rd = rn + 2048;
    int*   ri = (int*)(rd + 2048);
    int slot = warp_k * 4 + lq;
#pragma unroll
    for (int s = 0; s < 4; ++s) {
        int row = warp_m * 32 + (s >> 1) * 16 + gr + (s & 1) * 8;
        rn[row * 16 + slot] = bn[s];
        rd[row * 16 + slot] = bd[s];
        ri[row * 16 + slot] = bi[s];
    }
    __syncthreads();
    int* s_idx = (int*)(smc + SM_IDX);
    if (tid < 128) {
        float Bn = rn[tid * 16], Bd = rd[tid * 16];
        int Bi = ri[tid * 16];
#pragma unroll
        for (int g = 1; g < 16; ++g) {
            float cn = rn[tid * 16 + g], cd = rd[tid * 16 + g];
            int ci = ri[tid * 16 + g];
            float lhs = cn * Bd, rhs = Bn * cd;
            if (lhs < rhs || (lhs == rhs && ci < Bi)) { Bn = cn; Bd = cd; Bi = ci; }
        }
        s_idx[tid] = Bi;
        atomicAdd(out + OUT_DEN + Bi, OMG);
    }
    __syncthreads();

    // ---- gather codebook rows (stage over s_B) + EMA numer scatter ----
    float* s_g = (float*)(smc + SM_B);       // pitch 132
    const char* aimg = smc + SM_A;
    float* out_num = out + OUT_NUM;
    for (int t = tid; t < 4096; t += 512) {
        int n = t >> 5, d4 = (t & 31) << 2;
        int idx = s_idx[n];
        float4 ev = *(const float4*)(emb + idx * DD + d4);
        *(float4*)(s_g + n * 132 + d4) = ev;
        int o = img_off(n, d4);
        uint2 v0 = *(const uint2*)(aimg + o);
        uint2 v1 = *(const uint2*)(aimg + 32768 + o);
        uint2 v2 = *(const uint2*)(aimg + 65536 + o);
        float2 a0 = bf2f(v0.x), a1 = bf2f(v1.x), a2 = bf2f(v2.x);
        float2 b0 = bf2f(v0.y), b1 = bf2f(v1.y), b2 = bf2f(v2.y);
        float* dst = out_num + idx * DD + d4;
        atomicAdd(dst + 0, OMG * (a0.x + a1.x + a2.x));
        atomicAdd(dst + 1, OMG * (a0.y + a1.y + a2.y));
        atomicAdd(dst + 2, OMG * (b0.x + b1.x + b2.x));
        atomicAdd(dst + 3, OMG * (b0.y + b1.y + b2.y));
    }
    __syncthreads();

    // ---- write zq (coalesced float4 over n) ----
    float* out_zq = out + (size_t)b * DD * NNN + n0;
    for (int t = tid; t < 4096; t += 512) {
        int d = t >> 5, n4 = (t & 31) << 2;
        float4 q;
        q.x = s_g[(n4 + 0) * 132 + d];
        q.y = s_g[(n4 + 1) * 132 + d];
        q.z = s_g[(n4 + 2) * 132 + d];
        q.w = s_g[(n4 + 3) * 132 + d];
        *(float4*)(out_zq + (size_t)d * NNN + n4) = q;
    }
}

// ============================================================================
extern "C" void kernel_launch(void* const* d_in, const int* in_sizes, int n_in,
                              void* d_out, int out_size) {
    const float* z         = (const float*)d_in[0];
    const float* W_lin     = (const float*)d_in[1];
    const float* emb       = (const float*)d_in[2];
    const float* ema_numer = (const float*)d_in[3];
    const float* ema_denom = (const float*)d_in[4];
    float* out = (float*)d_out;

    const int ZE_SMEM = (128 * 256 + 128 * 32) * 4;   // 147456
    const int ZS_SMEM = 66048 + 3 * 32768;            // 164352

    cudaFuncSetAttribute(ze_kernel, cudaFuncAttributeMaxDynamicSharedMemorySize, ZE_SMEM);
    cudaFuncSetAttribute(zesplit_kernel, cudaFuncAttributeMaxDynamicSharedMemorySize, ZS_SMEM);
    cudaFuncSetAttribute(vq_kernel, cudaFuncAttributeMaxDynamicSharedMemorySize, VQ_SMEM);

    prep_kernel<<<264, 256>>>(emb, ema_numer, ema_denom, out);
    ze_kernel<<<dim3(NNN / 128, BB), 512, ZE_SMEM>>>(z, W_lin);
    zesplit_kernel<<<dim3(32, BB), 256, ZS_SMEM>>>();
    vq_kernel<<<dim3(32, BB), 512, VQ_SMEM>>>(emb, out);
}

// round 16
// speedup vs baseline: 1.0210x; 1.0210x over previous
#include <cuda_runtime.h>
#include <cuda_bf16.h>
#include <math.h>
#include <stdint.h>

#define BB 8
#define CC 256
#define DD 128
#define KK 1024
#define NNN 4096
#define GAMMA 0.99f
#define OMG 0.01f

#define OUT_NUM (BB*DD*NNN)          /* 4194304 */
#define OUT_DEN (OUT_NUM + KK*DD)    /* 4325376 */

typedef unsigned long long u64t;

// ---------------- device globals (no runtime alloc allowed) ----------------
__device__ __align__(128) float g_ze[BB*DD*NNN];                 // 16 MB fp32 ze
__device__ float g_qsq[KK], g_qs[KK];
__device__ float g_zesq[BB*NNN], g_za[BB*NNN];
__device__ __align__(128) __nv_bfloat16 g_emb3[8*3*128*128];     // emb split images
__device__ __align__(128) __nv_bfloat16 g_zt3[BB*32*3*128*128];  // ze^T split images

// packed fp32x2 FMA (ze kernel)
#define FMA2(acc, a, b) \
    asm("fma.rn.f32x2 %0, %1, %2, %0;" : "+l"(acc) : "l"(a), "l"(b))
__device__ __forceinline__ float fold2(u64t v) {
    float lo, hi;
    asm("mov.b64 {%0, %1}, %2;" : "=f"(lo), "=f"(hi) : "l"(v));
    return lo + hi;
}

__device__ __forceinline__ uint32_t smem_u32(const void* p) {
    uint32_t a;
    asm("{ .reg .u64 t; cvta.to.shared.u64 t, %1; cvt.u32.u64 %0, t; }" : "=r"(a) : "l"(p));
    return a;
}

// ---------------- mma.sync / ldmatrix (arch-generic, sm_80+) ----------------
#define LDSM4(r, addr) \
    asm volatile("ldmatrix.sync.aligned.m8n8.x4.shared.b16 {%0,%1,%2,%3}, [%4];" \
        : "=r"((r)[0]), "=r"((r)[1]), "=r"((r)[2]), "=r"((r)[3]) : "r"(addr))

#define MMA16816(c, a, b0, b1) \
    asm volatile("mma.sync.aligned.m16n8k16.row.col.f32.bf16.bf16.f32 " \
        "{%0,%1,%2,%3}, {%4,%5,%6,%7}, {%8,%9}, {%0,%1,%2,%3};" \
        : "+f"((c)[0]), "+f"((c)[1]), "+f"((c)[2]), "+f"((c)[3]) \
        : "r"((a)[0]), "r"((a)[1]), "r"((a)[2]), "r"((a)[3]), "r"(b0), "r"(b1))

// byte offset inside a 128x128-bf16 image: [r][d], 256B rows,
// 16B chunks XOR-swizzled by (r&7) -> conflict-free ldmatrix
__device__ __forceinline__ int img_off(int r, int c) {
    return r * 256 + ((((c >> 3) ^ (r & 7))) << 4) + ((c & 7) << 1);
}

__device__ __forceinline__ void split3(float x, __nv_bfloat16& e0,
                                       __nv_bfloat16& e1, __nv_bfloat16& e2) {
    e0 = __float2bfloat16(x);
    float r1 = x - __bfloat162float(e0);
    e1 = __float2bfloat16(r1);
    float r2 = r1 - __bfloat162float(e1);
    e2 = __float2bfloat16(r2);
}

__device__ __forceinline__ float2 bf2f(uint32_t u) {
    __nv_bfloat162 h = *reinterpret_cast<__nv_bfloat162*>(&u);
    return make_float2(__bfloat162float(h.x), __bfloat162float(h.y));
}

// ============================================================================
// prep: EMA init + codebook norms + emb bf16x3 split images
// ============================================================================
__global__ void prep_kernel(const float* __restrict__ emb,
                            const float* __restrict__ ema_numer,
                            const float* __restrict__ ema_denom,
                            float* __restrict__ out) {
    int bid = blockIdx.x, tid = threadIdx.x;
    if (bid < 128) {
        int idx = bid * 256 + tid;
        float4 v = reinterpret_cast<const float4*>(ema_numer)[idx];
        reinterpret_cast<float4*>(out + OUT_NUM)[idx] =
            make_float4(GAMMA * v.x, GAMMA * v.y, GAMMA * v.z, GAMMA * v.w);
    } else if (bid < 256) {
        int q = (bid - 128) * 8 + (tid >> 5);
        int lane = tid & 31;
        float4 v = reinterpret_cast<const float4*>(emb)[q * 32 + lane];
        float s = v.x * v.x + v.y * v.y + v.z * v.z + v.w * v.w;
#pragma unroll
        for (int o = 16; o; o >>= 1) s += __shfl_xor_sync(~0u, s, o);
        if (lane == 0) {
            g_qsq[q] = s;
            g_qs[q]  = sqrtf(s);
            out[OUT_DEN + q] = GAMMA * ema_denom[q];
        }
    } else {
        int kt = bid - 256;                       // code tile 0..7
        char* base = (char*)(g_emb3 + (size_t)kt * 3 * 16384);
        for (int t = tid; t < 128 * 128; t += 256) {
            int r = t >> 7, c = t & 127;
            float x = emb[(kt * 128 + r) * DD + c];
            __nv_bfloat16 e0, e1, e2;
            split3(x, e0, e1, e2);
            int o = img_off(r, c);
            *(__nv_bfloat16*)(base + o)         = e0;
            *(__nv_bfloat16*)(base + 32768 + o) = e1;
            *(__nv_bfloat16*)(base + 65536 + o) = e2;
        }
    }
}

// ============================================================================
// ze = W_lin @ z per batch (fp32 SIMT)
// ============================================================================
__global__ void __launch_bounds__(512)
ze_kernel(const float* __restrict__ z, const float* __restrict__ W) {
    extern __shared__ float sm[];
    float* sW = sm;
    float* sZ = sm + 128 * 256;
    int tid = threadIdx.x;
    int tx = tid & 31, ty = tid >> 5;
    int n0 = blockIdx.x * 128, b = blockIdx.y;
    int t7 = tx & 7;

#pragma unroll
    for (int t = 0; t < 16; ++t) {
        int v = tid + t * 512;
        reinterpret_cast<float4*>(sW)[v] = reinterpret_cast<const float4*>(W)[v];
    }

    u64t acc[8][4];
#pragma unroll
    for (int i = 0; i < 8; ++i)
#pragma unroll
        for (int j = 0; j < 4; ++j) acc[i][j] = 0ull;

    const float* zb = z + (size_t)b * CC * NNN + n0;
    for (int cc0 = 0; cc0 < CC; cc0 += 32) {
        __syncthreads();
#pragma unroll
        for (int t = 0; t < 2; ++t) {
            int v = tid + t * 512;
            int r = v >> 5, nn = (v & 31) << 2;
            float4 val = *reinterpret_cast<const float4*>(zb + (size_t)(cc0 + r) * NNN + nn);
            int c4 = r >> 2, cm = r & 3;
            sZ[(nn + 0) * 32 + ((c4 ^ ((nn + 0) & 7)) << 2) + cm] = val.x;
            sZ[(nn + 1) * 32 + ((c4 ^ ((nn + 1) & 7)) << 2) + cm] = val.y;
            sZ[(nn + 2) * 32 + ((c4 ^ ((nn + 2) & 7)) << 2) + cm] = val.z;
            sZ[(nn + 3) * 32 + ((c4 ^ ((nn + 3) & 7)) << 2) + cm] = val.w;
        }
        __syncthreads();
#pragma unroll
        for (int c4 = 0; c4 < 8; ++c4) {
            ulonglong2 zv[4];
#pragma unroll
            for (int j = 0; j < 4; ++j)
                zv[j] = *reinterpret_cast<const ulonglong2*>(
                    sZ + (32 * j + tx) * 32 + ((c4 ^ t7) << 2));
#pragma unroll
            for (int i = 0; i < 8; ++i) {
                ulonglong2 wv = *reinterpret_cast<const ulonglong2*>(
                    sW + (16 * i + ty) * 256 + cc0 + (c4 << 2));
#pragma unroll
                for (int j = 0; j < 4; ++j) {
                    FMA2(acc[i][j], wv.x, zv[j].x);
                    FMA2(acc[i][j], wv.y, zv[j].y);
                }
            }
        }
    }
    float* zo = g_ze + (size_t)b * DD * NNN + n0;
#pragma unroll
    for (int i = 0; i < 8; ++i)
#pragma unroll
        for (int j = 0; j < 4; ++j)
            zo[(size_t)(16 * i + ty) * NNN + 32 * j + tx] = fold2(acc[i][j]);
}

// ============================================================================
// zesplit: g_ze tile -> ze^T bf16x3 swizzled images + zesq/za
// ============================================================================
__global__ void __launch_bounds__(256)
zesplit_kernel() {
    extern __shared__ char smc[];
    float* s_f = (float*)smc;                 // [128][129] fp32
    char*  s_img = smc + 66048;               // 3 x 32768 images
    int tid = threadIdx.x;
    int b = blockIdx.y, nt = blockIdx.x, n0 = nt * 128;
    const float* zeg = g_ze + (size_t)b * DD * NNN + n0;

    for (int t = tid; t < 4096; t += 256) {
        int d = t >> 5, n4 = (t & 31) << 2;
        float4 v = *(const float4*)(zeg + (size_t)d * NNN + n4);
        float* row = s_f + d * 129;
        row[n4] = v.x; row[n4 + 1] = v.y; row[n4 + 2] = v.z; row[n4 + 3] = v.w;
    }
    __syncthreads();

    int n = tid & 127, dh = (tid >> 7) << 6;
    float ssum = 0.f;
#pragma unroll 4
    for (int dd = 0; dd < 64; ++dd) {
        int d = dh + dd;
        float x = s_f[d * 129 + n];
        ssum += x * x;
        __nv_bfloat16 e0, e1, e2;
        split3(x, e0, e1, e2);
        int o = img_off(n, d);
        *(__nv_bfloat16*)(s_img + o)         = e0;
        *(__nv_bfloat16*)(s_img + 32768 + o) = e1;
        *(__nv_bfloat16*)(s_img + 65536 + o) = e2;
    }
    __syncthreads();
    ((float*)smc)[tid] = ssum;
    __syncthreads();
    uint4* dst = (uint4*)(g_zt3 + (size_t)(b * 32 + nt) * 3 * 16384);
    const uint4* src = (const uint4*)s_img;
    for (int t = tid; t < 6144; t += 256) dst[t] = src[t];
    if (tid < 128) {
        float s = ((float*)smc)[tid] + ((float*)smc)[tid + 128];
        g_zesq[b * NNN + n0 + tid] = s;
        g_za[b * NNN + n0 + tid]   = sqrtf(s);
    }
}

// ============================================================================
// vq: HMMA bf16x3 error-free GEMM + argmin + gather + EMA scatter
// grid (32, 8), 512 threads (16 warps = 4m x 4k), ~196 KB smem
// ============================================================================
#define SM_QSQ  0
#define SM_QS   512
#define SM_ZESQ 1024
#define SM_ZA   1536
#define SM_IDX  2048
#define SM_A    4096
#define SM_B    102400
#define VQ_SMEM 200704

__global__ void __launch_bounds__(512)
vq_kernel(const float* __restrict__ emb, float* __restrict__ out) {
    extern __shared__ char smc[];
    uint32_t sb = smem_u32(smc);
    int tid = threadIdx.x, l = tid & 31, wid = tid >> 5;
    int b = blockIdx.y, nt = blockIdx.x, n0 = nt * 128;

    // prologue: A (ze^T) images + zesq/za
    {
        const uint4* asrc = (const uint4*)(g_zt3 + (size_t)(b * 32 + nt) * 3 * 16384);
        uint4* adst = (uint4*)(smc + SM_A);
        for (int t = tid; t < 6144; t += 512) adst[t] = asrc[t];
        if (tid < 128) {
            ((float*)(smc + SM_ZESQ))[tid] = g_zesq[b * NNN + n0 + tid];
            ((float*)(smc + SM_ZA))[tid]   = g_za[b * NNN + n0 + tid];
        }
    }
    __syncthreads();

    int warp_m = wid & 3, warp_k = wid >> 2;
    int sub = l >> 3, l7 = l & 7, lq = l & 3, gr = l >> 2;
    uint32_t xA = (uint32_t)(sub >> 1), xB = (uint32_t)(sub & 1);
    uint32_t abase0 = sb + SM_A + (uint32_t)(warp_m * 32 + (sub & 1) * 8 + l7) * 256;
    uint32_t abase1 = abase0 + 16 * 256;
    uint32_t bbase0 = sb + SM_B + (uint32_t)(warp_k * 32 + (sub >> 1) * 8 + l7) * 256;
    uint32_t bbase1 = bbase0 + 16 * 256;

    float zesq_r[4], za_r[4];
#pragma unroll
    for (int s = 0; s < 4; ++s) {
        int row = warp_m * 32 + (s >> 1) * 16 + gr + (s & 1) * 8;
        zesq_r[s] = ((float*)(smc + SM_ZESQ))[row];
        za_r[s]   = ((float*)(smc + SM_ZA))[row];
    }

    float bn[4], bd[4];
    int bi[4];
#pragma unroll
    for (int s = 0; s < 4; ++s) { bn[s] = 1e30f; bd[s] = 1.f; bi[s] = 0; }

    int jb = warp_k * 32 + 2 * lq;

    for (int kt = 0; kt < 8; ++kt) {
        __syncthreads();
        {
            const uint4* bsrc = (const uint4*)(g_emb3 + (size_t)kt * 3 * 16384);
            uint4* bdst = (uint4*)(smc + SM_B);
            for (int t = tid; t < 6144; t += 512) bdst[t] = bsrc[t];
            if (tid < 128) {
                ((float*)(smc + SM_QSQ))[tid] = g_qsq[kt * 128 + tid];
                ((float*)(smc + SM_QS))[tid]  = g_qs[kt * 128 + tid];
            }
        }
        __syncthreads();

        float acc[2][4][4];
#pragma unroll
        for (int mi = 0; mi < 2; ++mi)
#pragma unroll
            for (int ni = 0; ni < 4; ++ni)
#pragma unroll
                for (int c = 0; c < 4; ++c) acc[mi][ni][c] = 0.f;

#define MMA_ALL(B0, B1) do { \
        MMA16816(acc[0][0], A0, B0[0], B0[1]); \
        MMA16816(acc[0][1], A0, B0[2], B0[3]); \
        MMA16816(acc[0][2], A0, B1[0], B1[1]); \
        MMA16816(acc[0][3], A0, B1[2], B1[3]); \
        MMA16816(acc[1][0], A1, B0[0], B0[1]); \
        MMA16816(acc[1][1], A1, B0[2], B0[3]); \
        MMA16816(acc[1][2], A1, B1[0], B1[1]); \
        MMA16816(acc[1][3], A1, B1[2], B1[3]); } while (0)

#pragma unroll
        for (int ks = 0; ks < 8; ++ks) {
            uint32_t ca = (uint32_t)(((2 * ks + xA) ^ (uint32_t)l7) << 4);
            uint32_t cb = (uint32_t)(((2 * ks + xB) ^ (uint32_t)l7) << 4);
            uint32_t A0[4], A1[4], B0[4], B1[4];
            // p = 0 : q = 0,1,2
            LDSM4(A0, abase0 + ca); LDSM4(A1, abase1 + ca);
            LDSM4(B0, bbase0 + cb);           LDSM4(B1, bbase1 + cb);           MMA_ALL(B0, B1);
            LDSM4(B0, bbase0 + 32768 + cb);   LDSM4(B1, bbase1 + 32768 + cb);   MMA_ALL(B0, B1);
            LDSM4(B0, bbase0 + 65536 + cb);   LDSM4(B1, bbase1 + 65536 + cb);   MMA_ALL(B0, B1);
            // p = 1 : q = 0,1
            LDSM4(A0, abase0 + 32768 + ca); LDSM4(A1, abase1 + 32768 + ca);
            LDSM4(B0, bbase0 + cb);           LDSM4(B1, bbase1 + cb);           MMA_ALL(B0, B1);
            LDSM4(B0, bbase0 + 32768 + cb);   LDSM4(B1, bbase1 + 32768 + cb);   MMA_ALL(B0, B1);
            // p = 2 : q = 0
            LDSM4(A0, abase0 + 65536 + ca); LDSM4(A1, abase1 + 65536 + ca);
            LDSM4(B0, bbase0 + cb);           LDSM4(B1, bbase1 + cb);           MMA_ALL(B0, B1);
        }

        // argmin update from c-fragments
        float qq[4][2], qn[4][2];
#pragma unroll
        for (int ni = 0; ni < 4; ++ni)
#pragma unroll
            for (int c = 0; c < 2; ++c) {
                int j = jb + ni * 8 + c;
                qq[ni][c] = ((float*)(smc + SM_QSQ))[j];
                qn[ni][c] = ((float*)(smc + SM_QS))[j];
            }
#pragma unroll
        for (int mi = 0; mi < 2; ++mi)
#pragma unroll
            for (int h = 0; h < 2; ++h) {
                int s = mi * 2 + h;
#pragma unroll
                for (int ni = 0; ni < 4; ++ni)
#pragma unroll
                    for (int c = 0; c < 2; ++c) {
                        float dot = acc[mi][ni][2 * h + c];
                        float num = fmaxf(zesq_r[s] + qq[ni][c] - 2.f * dot, 0.f);
                        float den = za_r[s] + qn[ni][c];
                        float d2 = den * den;
                        if (num * bd[s] < bn[s] * d2) {
                            bn[s] = num; bd[s] = d2;
                            bi[s] = kt * 128 + jb + ni * 8 + c;
                        }
                    }
            }
    }
    __syncthreads();

    // ---- cross-thread argmin reduction (overlay on s_B) ----
    float* rn = (float*)(smc + SM_B);
    float* rd = rn + 2048;
    int*   ri = (int*)(rd + 2048);
    int slot = warp_k * 4 + lq;
#pragma unroll
    for (int s = 0; s < 4; ++s) {
        int row = warp_m * 32 + (s >> 1) * 16 + gr + (s & 1) * 8;
        rn[row * 16 + slot] = bn[s];
        rd[row * 16 + slot] = bd[s];
        ri[row * 16 + slot] = bi[s];
    }
    __syncthreads();
    int* s_idx = (int*)(smc + SM_IDX);
    if (tid < 128) {
        float Bn = rn[tid * 16], Bd = rd[tid * 16];
        int Bi = ri[tid * 16];
#pragma unroll
        for (int g = 1; g < 16; ++g) {
            float cn = rn[tid * 16 + g], cd = rd[tid * 16 + g];
            int ci = ri[tid * 16 + g];
            float lhs = cn * Bd, rhs = Bn * cd;
            if (lhs < rhs || (lhs == rhs && ci < Bi)) { Bn = cn; Bd = cd; Bi = ci; }
        }
        s_idx[tid] = Bi;
        atomicAdd(out + OUT_DEN + Bi, OMG);
    }
    __syncthreads();

    // ---- gather codebook rows (stage over s_B) + EMA numer scatter ----
    float* s_g = (float*)(smc + SM_B);       // pitch 132
    const char* aimg = smc + SM_A;
    float* out_num = out + OUT_NUM;
    for (int t = tid; t < 4096; t += 512) {
        int n = t >> 5, d4 = (t & 31) << 2;
        int idx = s_idx[n];
        float4 ev = *(const float4*)(emb + idx * DD + d4);
        *(float4*)(s_g + n * 132 + d4) = ev;
        int o = img_off(n, d4);
        uint2 v0 = *(const uint2*)(aimg + o);
        uint2 v1 = *(const uint2*)(aimg + 32768 + o);
        uint2 v2 = *(const uint2*)(aimg + 65536 + o);
        float2 a0 = bf2f(v0.x), a1 = bf2f(v1.x), a2 = bf2f(v2.x);
        float2 b0 = bf2f(v0.y), b1 = bf2f(v1.y), b2 = bf2f(v2.y);
        float* dst = out_num + idx * DD + d4;
        atomicAdd(dst + 0, OMG * (a0.x + a1.x + a2.x));
        atomicAdd(dst + 1, OMG * (a0.y + a1.y + a2.y));
        atomicAdd(dst + 2, OMG * (b0.x + b1.x + b2.x));
        atomicAdd(dst + 3, OMG * (b0.y + b1.y + b2.y));
    }
    __syncthreads();

    // ---- write zq (coalesced float4 over n) ----
    float* out_zq = out + (size_t)b * DD * NNN + n0;
    for (int t = tid; t < 4096; t += 512) {
        int d = t >> 5, n4 = (t & 31) << 2;
        float4 q;
        q.x = s_g[(n4 + 0) * 132 + d];
        q.y = s_g[(n4 + 1) * 132 + d];
        q.z = s_g[(n4 + 2) * 132 + d];
        q.w = s_g[(n4 + 3) * 132 + d];
        *(float4*)(out_zq + (size_t)d * NNN + n4) = q;
    }
}

// ============================================================================
extern "C" void kernel_launch(void* const* d_in, const int* in_sizes, int n_in,
                              void* d_out, int out_size) {
    const float* z         = (const float*)d_in[0];
    const float* W_lin     = (const float*)d_in[1];
    const float* emb       = (const float*)d_in[2];
    const float* ema_numer = (const float*)d_in[3];
    const float* ema_denom = (const float*)d_in[4];
    float* out = (float*)d_out;

    const int ZE_SMEM = (128 * 256 + 128 * 32) * 4;   // 147456
    const int ZS_SMEM = 66048 + 3 * 32768;            // 164352

    cudaFuncSetAttribute(ze_kernel, cudaFuncAttributeMaxDynamicSharedMemorySize, ZE_SMEM);
    cudaFuncSetAttribute(zesplit_kernel, cudaFuncAttributeMaxDynamicSharedMemorySize, ZS_SMEM);
    cudaFuncSetAttribute(vq_kernel, cudaFuncAttributeMaxDynamicSharedMemorySize, VQ_SMEM);

    prep_kernel<<<264, 256>>>(emb, ema_numer, ema_denom, out);
    ze_kernel<<<dim3(NNN / 128, BB), 512, ZE_SMEM>>>(z, W_lin);
    zesplit_kernel<<<dim3(32, BB), 256, ZS_SMEM>>>();
    vq_kernel<<<dim3(32, BB), 512, VQ_SMEM>>>(emb, out);
}